// round 13
// baseline (speedup 1.0000x reference)
#include <cuda_runtime.h>
#include <stdint.h>

// embeddings: [B=32, L=4, W=512, D=768] f32; segment_ids: [B=32, W=512] i32 sorted/row.
// Out (f32, concat): word [B, D, W] then sent [B, D].
//
// word[b,d,s] = (1/L) * sum_{w: seg[b,w]==s} sum_l emb[b,l,w,d]
// sent[b,d]   = (1/W) * sum_s word[b,d,s]
//
// R12: revert to R10 operating point (27KB smem, depth-1 explicit pipeline,
// barrier-free main loop) + amortize the block prologue: each block now
// processes TWO s-tiles of the same (b, d-half), reusing segs and the
// single tile_s buffer. launch_bounds(96,7) -> 7 blocks/SM; grid 1024 is
// fully resident in ~one wave.

#define BB 32
#define LL 4
#define WW 512
#define DD 768

#define TILE_S 16          // segments per tile
#define NTILES 2           // s-tiles per block
#define NTHR   96          // threads per block
#define TILE_D (NTHR * 4)  // 384 d-channels per block (float4/thread)
#define TS_ST  388         // tile_s row stride (floats)

__global__ void zero_sent_kernel(float* __restrict__ sent) {
    int i = blockIdx.x * blockDim.x + threadIdx.x;
    if (i < BB * DD) sent[i] = 0.0f;
}

__device__ __forceinline__ float4 sum4(float4 a, float4 b, float4 c, float4 d) {
    float4 r;
    r.x = (a.x + b.x) + (c.x + d.x);
    r.y = (a.y + b.y) + (c.y + d.y);
    r.z = (a.z + b.z) + (c.z + d.z);
    r.w = (a.w + b.w) + (c.w + d.w);
    return r;
}

__global__ __launch_bounds__(NTHR, 7)
void word_agg_kernel(const float* __restrict__ emb,
                     const int*   __restrict__ seg,
                     float*       __restrict__ word,   // [B, D, W]
                     float*       __restrict__ sent)   // [B, D]
{
    __shared__ float tile_s[TILE_S][TS_ST];   // 16 x 388 x 4B = 24,832 B
    __shared__ int   segs[WW];                // 2,048 B

    const int b      = blockIdx.z;
    const int s_base = blockIdx.y * (TILE_S * NTILES);
    const int d0     = blockIdx.x * TILE_D;
    const int tid    = threadIdx.x;
    const int lane   = tid & 31;

    #pragma unroll
    for (int i = tid; i < WW; i += NTHR) segs[i] = seg[b * WW + i];

    // Zero thread-owned tile_s columns (no cooperative zero needed: column
    // [*][tid] is written and read only by this thread until the transpose).
    #pragma unroll
    for (int s = 0; s < TILE_S; ++s)
        ((float4*)&tile_s[s][0])[tid] = make_float4(0.f, 0.f, 0.f, 0.f);

    __syncthreads();   // segs visible to all

    const float* __restrict__ base = emb + ((size_t)b * LL * WW) * DD + d0 + tid * 4;
    const size_t LSTRIDE = (size_t)WW * DD;
    const float  k_sent  = 0.25f / (float)WW;
    float* sp = sent + b * DD + d0 + tid * 4;

    float4 cs_tot = make_float4(0.f, 0.f, 0.f, 0.f);   // sent accumulator

    #pragma unroll
    for (int t = 0; t < NTILES; ++t) {
        const int s0 = s_base + t * TILE_S;

        // Per-warp boundary scan: unique i with segs[i-1] < bound <= segs[i].
        int wlo = WW, whi = WW;
        #pragma unroll
        for (int i = lane; i < WW; i += 32) {
            const int v    = segs[i];
            const int prev = (i == 0) ? -1 : segs[i - 1];
            if (prev < s0          && v >= s0)          wlo = i;
            if (prev < s0 + TILE_S && v >= s0 + TILE_S) whi = i;
        }
        wlo = __reduce_min_sync(0xffffffffu, wlo);
        whi = __reduce_min_sync(0xffffffffu, whi);

        // RMW accumulate into the thread-owned tile_s column.
        auto rmw = [&](int widx, float4 v) {
            float4* row = (float4*)&tile_s[segs[widx] - s0][0];
            float4 t0 = row[tid];
            t0.x += v.x; t0.y += v.y; t0.z += v.z; t0.w += v.w;
            row[tid] = t0;
        };

        int w = wlo;
        if (w + 1 < whi) {
            // Depth-1 pipeline prologue: pair (w, w+1) -> 8 LDG.128 in flight.
            const float* p0 = base + (size_t)w * DD;
            const float* p1 = p0 + DD;
            float4 c0 = *(const float4*)(p0);
            float4 c1 = *(const float4*)(p0 + LSTRIDE);
            float4 c2 = *(const float4*)(p0 + 2 * LSTRIDE);
            float4 c3 = *(const float4*)(p0 + 3 * LSTRIDE);
            float4 c4 = *(const float4*)(p1);
            float4 c5 = *(const float4*)(p1 + LSTRIDE);
            float4 c6 = *(const float4*)(p1 + 2 * LSTRIDE);
            float4 c7 = *(const float4*)(p1 + 3 * LSTRIDE);

            for (; w + 3 < whi; w += 2) {
                const float* q0 = base + (size_t)(w + 2) * DD;
                const float* q1 = q0 + DD;
                float4 n0 = *(const float4*)(q0);
                float4 n1 = *(const float4*)(q0 + LSTRIDE);
                float4 n2 = *(const float4*)(q0 + 2 * LSTRIDE);
                float4 n3 = *(const float4*)(q0 + 3 * LSTRIDE);
                float4 n4 = *(const float4*)(q1);
                float4 n5 = *(const float4*)(q1 + LSTRIDE);
                float4 n6 = *(const float4*)(q1 + 2 * LSTRIDE);
                float4 n7 = *(const float4*)(q1 + 3 * LSTRIDE);

                rmw(w,     sum4(c0, c1, c2, c3));
                rmw(w + 1, sum4(c4, c5, c6, c7));

                c0 = n0; c1 = n1; c2 = n2; c3 = n3;
                c4 = n4; c5 = n5; c6 = n6; c7 = n7;
            }
            rmw(w,     sum4(c0, c1, c2, c3));
            rmw(w + 1, sum4(c4, c5, c6, c7));
            w += 2;
        }
        for (; w < whi; ++w) {
            const float* p = base + (size_t)w * DD;
            float4 e0 = *(const float4*)(p);
            float4 e1 = *(const float4*)(p + LSTRIDE);
            float4 e2 = *(const float4*)(p + 2 * LSTRIDE);
            float4 e3 = *(const float4*)(p + 3 * LSTRIDE);
            rmw(w, sum4(e0, e1, e2, e3));
        }

        // Fold this tile into the sent accumulator (thread-owned columns).
        #pragma unroll
        for (int s = 0; s < TILE_S; ++s) {
            float4 v = ((const float4*)&tile_s[s][0])[tid];
            cs_tot.x += v.x; cs_tot.y += v.y; cs_tot.z += v.z; cs_tot.w += v.w;
        }

        __syncthreads();   // handoff: transpose reads cross-thread columns

        // Transposed coalesced write: word[b, d0+dd, s0 + ss4*4 .. +3].
        float* __restrict__ outb = word + ((size_t)b * DD + d0) * WW + s0;
        const int NOUT = (TILE_S / 4) * TILE_D;   // 1536 float4 stores
        for (int i2 = tid; i2 < NOUT; i2 += NTHR) {
            const int ss4 = i2 & 3;
            const int dd  = i2 >> 2;
            float4 v;
            v.x = 0.25f * tile_s[ss4 * 4 + 0][dd];
            v.y = 0.25f * tile_s[ss4 * 4 + 1][dd];
            v.z = 0.25f * tile_s[ss4 * 4 + 2][dd];
            v.w = 0.25f * tile_s[ss4 * 4 + 3][dd];
            *(float4*)(outb + (size_t)dd * WW + ss4 * 4) = v;
        }

        if (t + 1 < NTILES) {
            __syncthreads();   // all transpose reads done before re-zero
            #pragma unroll
            for (int s = 0; s < TILE_S; ++s)
                ((float4*)&tile_s[s][0])[tid] = make_float4(0.f, 0.f, 0.f, 0.f);
            // No barrier needed: next tile's rmw touches only column [*][tid].
        }
    }

    // sent: one atomic set per thread for the whole block.
    atomicAdd(sp + 0, cs_tot.x * k_sent);
    atomicAdd(sp + 1, cs_tot.y * k_sent);
    atomicAdd(sp + 2, cs_tot.z * k_sent);
    atomicAdd(sp + 3, cs_tot.w * k_sent);
}

extern "C" void kernel_launch(void* const* d_in, const int* in_sizes, int n_in,
                              void* d_out, int out_size) {
    const float* emb = (const float*)d_in[0];
    const int*   seg = (const int*)d_in[1];

    float* word = (float*)d_out;                   // [B, D, W]
    float* sent = word + (size_t)BB * DD * WW;     // [B, D]

    zero_sent_kernel<<<(BB * DD + 255) / 256, 256>>>(sent);

    dim3 grid(DD / TILE_D, WW / (TILE_S * NTILES), BB);  // (2, 16, 32) = 1024
    word_agg_kernel<<<grid, NTHR>>>(emb, seg, word, sent);
}

// round 14
// speedup vs baseline: 1.0537x; 1.0537x over previous
#include <cuda_runtime.h>
#include <stdint.h>

// embeddings: [B=32, L=4, W=512, D=768] f32; segment_ids: [B=32, W=512] i32 sorted/row.
// Out (f32, concat): word [B, D, W] then sent [B, D].
//
// word[b,d,s] = (1/L) * sum_{w: seg[b,w]==s} sum_l emb[b,l,w,d]
// sent[b,d]   = (1/W) * sum_s word[b,d,s]
//
// R13: prologue elimination. Setup kernel precomputes per-(b, s-tile) w-range
// boundaries; main blocks read 2 uniform ints, fetch seg ids as warp-uniform
// cached LDG.32 per iteration, and zero only thread-owned smem columns ->
// ZERO barriers before streaming (single barrier before the output
// transpose). Streaming core = R11's depth-1 explicit pipeline (8 LDG.128
// structurally in flight per thread).

#define BB 32
#define LL 4
#define WW 512
#define DD 768

#define TILE_S 16          // segments per block
#define NT     (WW / TILE_S)  // 32 s-tiles per row
#define NTHR   96          // threads per block
#define TILE_D (NTHR * 4)  // 384 d-channels per block (float4/thread)
#define TS_ST  388         // tile_s row stride (floats)

// bounds[b][t] = first w with seg[b,w] >= t*TILE_S (== W if none).
// whi of tile t == bounds[b][t+1].
__device__ int g_bounds[BB][NT + 1];

__global__ void setup_kernel(const int* __restrict__ seg,
                             float* __restrict__ sent) {
    const int b   = blockIdx.x;
    const int tid = threadIdx.x;   // 512 threads

    // zero sent (24576 floats across 32 blocks)
    for (int i = b * blockDim.x + tid; i < BB * DD; i += gridDim.x * blockDim.x)
        sent[i] = 0.0f;

    if (tid <= NT) g_bounds[b][tid] = WW;   // default: empty / past end
    __syncthreads();

    const int v    = seg[b * WW + tid];
    const int prev = (tid == 0) ? -1 : seg[b * WW + tid - 1];
    // tid is the lower bound of every t*TILE_S in (prev, v].
    const int t_lo = (prev < 0) ? 0 : (prev / TILE_S + 1);
    const int t_hi = v / TILE_S;            // t*TILE_S <= v  <=>  t <= v/TILE_S
    for (int t = t_lo; t <= t_hi && t <= NT; ++t)
        g_bounds[b][t] = tid;
}

__device__ __forceinline__ float4 sum4(float4 a, float4 b, float4 c, float4 d) {
    float4 r;
    r.x = (a.x + b.x) + (c.x + d.x);
    r.y = (a.y + b.y) + (c.y + d.y);
    r.z = (a.z + b.z) + (c.z + d.z);
    r.w = (a.w + b.w) + (c.w + d.w);
    return r;
}

__global__ __launch_bounds__(NTHR)
void word_agg_kernel(const float* __restrict__ emb,
                     const int*   __restrict__ seg,
                     float*       __restrict__ word,   // [B, D, W]
                     float*       __restrict__ sent)   // [B, D]
{
    __shared__ float tile_s[TILE_S][TS_ST];   // 16 x 388 x 4B = 24,832 B

    const int b   = blockIdx.z;
    const int ty  = blockIdx.y;               // s-tile index
    const int s0  = ty * TILE_S;
    const int d0  = blockIdx.x * TILE_D;
    const int tid = threadIdx.x;

    // Zero thread-owned tile_s columns: column [*][tid] is written and read
    // only by this thread until the transpose -> NO barrier needed.
    #pragma unroll
    for (int s = 0; s < TILE_S; ++s)
        ((float4*)&tile_s[s][0])[tid] = make_float4(0.f, 0.f, 0.f, 0.f);

    // Precomputed w-range: 2 uniform cached loads, no scan, no barrier.
    const int wlo = __ldg(&g_bounds[b][ty]);
    const int whi = __ldg(&g_bounds[b][ty + 1]);

    const float* __restrict__ base = emb + ((size_t)b * LL * WW) * DD + d0 + tid * 4;
    const int*   __restrict__ segr = seg + b * WW;
    const size_t LSTRIDE = (size_t)WW * DD;

    // RMW accumulate into the thread-owned tile_s column. seg fetch is
    // warp-uniform (broadcast sector, L1-resident: 64 blocks reuse each row).
    auto rmw = [&](int widx, float4 v) {
        float4* row = (float4*)&tile_s[__ldg(segr + widx) - s0][0];
        float4 t = row[tid];
        t.x += v.x; t.y += v.y; t.z += v.z; t.w += v.w;
        row[tid] = t;
    };

    int w = wlo;
    if (w + 1 < whi) {
        // Depth-1 pipeline prologue: pair (w, w+1) -> 8 LDG.128 in flight.
        const float* p0 = base + (size_t)w * DD;
        const float* p1 = p0 + DD;
        float4 c0 = *(const float4*)(p0);
        float4 c1 = *(const float4*)(p0 + LSTRIDE);
        float4 c2 = *(const float4*)(p0 + 2 * LSTRIDE);
        float4 c3 = *(const float4*)(p0 + 3 * LSTRIDE);
        float4 c4 = *(const float4*)(p1);
        float4 c5 = *(const float4*)(p1 + LSTRIDE);
        float4 c6 = *(const float4*)(p1 + 2 * LSTRIDE);
        float4 c7 = *(const float4*)(p1 + 3 * LSTRIDE);

        for (; w + 3 < whi; w += 2) {
            const float* q0 = base + (size_t)(w + 2) * DD;
            const float* q1 = q0 + DD;
            float4 n0 = *(const float4*)(q0);
            float4 n1 = *(const float4*)(q0 + LSTRIDE);
            float4 n2 = *(const float4*)(q0 + 2 * LSTRIDE);
            float4 n3 = *(const float4*)(q0 + 3 * LSTRIDE);
            float4 n4 = *(const float4*)(q1);
            float4 n5 = *(const float4*)(q1 + LSTRIDE);
            float4 n6 = *(const float4*)(q1 + 2 * LSTRIDE);
            float4 n7 = *(const float4*)(q1 + 3 * LSTRIDE);

            rmw(w,     sum4(c0, c1, c2, c3));
            rmw(w + 1, sum4(c4, c5, c6, c7));

            c0 = n0; c1 = n1; c2 = n2; c3 = n3;
            c4 = n4; c5 = n5; c6 = n6; c7 = n7;
        }
        rmw(w,     sum4(c0, c1, c2, c3));
        rmw(w + 1, sum4(c4, c5, c6, c7));
        w += 2;
    }
    for (; w < whi; ++w) {
        const float* p = base + (size_t)w * DD;
        float4 e0 = *(const float4*)(p);
        float4 e1 = *(const float4*)(p + LSTRIDE);
        float4 e2 = *(const float4*)(p + 2 * LSTRIDE);
        float4 e3 = *(const float4*)(p + 3 * LSTRIDE);
        rmw(w, sum4(e0, e1, e2, e3));
    }

    // sent contribution (thread-owned columns, still barrier-free).
    {
        float4 cs = make_float4(0.f, 0.f, 0.f, 0.f);
        #pragma unroll
        for (int s = 0; s < TILE_S; ++s) {
            float4 v = ((const float4*)&tile_s[s][0])[tid];
            cs.x += v.x; cs.y += v.y; cs.z += v.z; cs.w += v.w;
        }
        const float k = 0.25f / (float)WW;
        float* sp = sent + b * DD + d0 + tid * 4;
        atomicAdd(sp + 0, cs.x * k);
        atomicAdd(sp + 1, cs.y * k);
        atomicAdd(sp + 2, cs.z * k);
        atomicAdd(sp + 3, cs.w * k);
    }

    __syncthreads();   // the ONLY barrier: transpose reads cross-thread data

    // Transposed coalesced write: word[b, d0+dd, s0 + ss4*4 .. +3] as float4.
    float* __restrict__ outb = word + ((size_t)b * DD + d0) * WW + s0;
    const int NOUT = (TILE_S / 4) * TILE_D;   // 1536 float4 stores
    for (int i2 = tid; i2 < NOUT; i2 += NTHR) {
        const int ss4 = i2 & 3;
        const int dd  = i2 >> 2;
        float4 v;
        v.x = 0.25f * tile_s[ss4 * 4 + 0][dd];
        v.y = 0.25f * tile_s[ss4 * 4 + 1][dd];
        v.z = 0.25f * tile_s[ss4 * 4 + 2][dd];
        v.w = 0.25f * tile_s[ss4 * 4 + 3][dd];
        *(float4*)(outb + (size_t)dd * WW + ss4 * 4) = v;
    }
}

extern "C" void kernel_launch(void* const* d_in, const int* in_sizes, int n_in,
                              void* d_out, int out_size) {
    const float* emb = (const float*)d_in[0];
    const int*   seg = (const int*)d_in[1];

    float* word = (float*)d_out;                   // [B, D, W]
    float* sent = word + (size_t)BB * DD * WW;     // [B, D]

    setup_kernel<<<BB, WW>>>(seg, sent);

    dim3 grid(DD / TILE_D, NT, BB);                // (2, 32, 32) = 2048 blocks
    word_agg_kernel<<<grid, NTHR>>>(emb, seg, word, sent);
}

// round 15
// speedup vs baseline: 1.1117x; 1.0551x over previous
#include <cuda_runtime.h>
#include <stdint.h>

// embeddings: [B=32, L=4, W=512, D=768] f32; segment_ids: [B=32, W=512] i32 sorted/row.
// Out (f32, concat): word [B, D, W] then sent [B, D].
//
// word[b,d,s] = (1/L) * sum_{w: seg[b,w]==s} sum_l emb[b,l,w,d]
// sent[b,d]   = (1/W) * sum_s word[b,d,s]
//
// R14 = R13 (precomputed tile bounds, zero-barrier prologue, thread-owned
// smem columns, single barrier) + seg indices pipelined through registers
// with the same one-pair lookahead as the data. Nothing with global-load
// latency sits on the consume path.

#define BB 32
#define LL 4
#define WW 512
#define DD 768

#define TILE_S 16             // segments per block
#define NT     (WW / TILE_S)  // 32 s-tiles per row
#define NTHR   96             // threads per block
#define TILE_D (NTHR * 4)     // 384 d-channels per block (float4/thread)
#define TS_ST  388            // tile_s row stride (floats)

// bounds[b][t] = first w with seg[b,w] >= t*TILE_S (== W if none).
__device__ int g_bounds[BB][NT + 1];

__global__ void setup_kernel(const int* __restrict__ seg,
                             float* __restrict__ sent) {
    const int b   = blockIdx.x;
    const int tid = threadIdx.x;   // 512 threads

    for (int i = b * blockDim.x + tid; i < BB * DD; i += gridDim.x * blockDim.x)
        sent[i] = 0.0f;

    if (tid <= NT) g_bounds[b][tid] = WW;
    __syncthreads();

    const int v    = seg[b * WW + tid];
    const int prev = (tid == 0) ? -1 : seg[b * WW + tid - 1];
    const int t_lo = (prev < 0) ? 0 : (prev / TILE_S + 1);
    const int t_hi = v / TILE_S;
    for (int t = t_lo; t <= t_hi && t <= NT; ++t)
        g_bounds[b][t] = tid;
}

__device__ __forceinline__ float4 sum4(float4 a, float4 b, float4 c, float4 d) {
    float4 r;
    r.x = (a.x + b.x) + (c.x + d.x);
    r.y = (a.y + b.y) + (c.y + d.y);
    r.z = (a.z + b.z) + (c.z + d.z);
    r.w = (a.w + b.w) + (c.w + d.w);
    return r;
}

__global__ __launch_bounds__(NTHR)
void word_agg_kernel(const float* __restrict__ emb,
                     const int*   __restrict__ seg,
                     float*       __restrict__ word,   // [B, D, W]
                     float*       __restrict__ sent)   // [B, D]
{
    __shared__ float tile_s[TILE_S][TS_ST];   // 16 x 388 x 4B = 24,832 B

    const int b   = blockIdx.z;
    const int ty  = blockIdx.y;               // s-tile index
    const int s0  = ty * TILE_S;
    const int d0  = blockIdx.x * TILE_D;
    const int tid = threadIdx.x;

    // Zero thread-owned tile_s columns — no barrier needed (column [*][tid]
    // is written and read only by this thread until the transpose).
    #pragma unroll
    for (int s = 0; s < TILE_S; ++s)
        ((float4*)&tile_s[s][0])[tid] = make_float4(0.f, 0.f, 0.f, 0.f);

    // Precomputed w-range: 2 uniform cached loads, no scan, no barrier.
    const int wlo = __ldg(&g_bounds[b][ty]);
    const int whi = __ldg(&g_bounds[b][ty + 1]);

    const float* __restrict__ base = emb + ((size_t)b * LL * WW) * DD + d0 + tid * 4;
    const int*   __restrict__ segr = seg + b * WW;
    const size_t LSTRIDE = (size_t)WW * DD;

    // Consume path: pure register -> LDS/FADD/STS (seg index already in reg).
    auto rmw = [&](int sidx, float4 v) {
        float4* row = (float4*)&tile_s[sidx - s0][0];
        float4 t = row[tid];
        t.x += v.x; t.y += v.y; t.z += v.z; t.w += v.w;
        row[tid] = t;
    };

    int w = wlo;
    if (w + 1 < whi) {
        // Pipeline prologue: data pair (w, w+1) = 8 LDG.128, plus the pair's
        // seg indices — ALL in flight before any consume.
        const float* p0 = base + (size_t)w * DD;
        const float* p1 = p0 + DD;
        int sg0 = __ldg(segr + w);
        int sg1 = __ldg(segr + w + 1);
        float4 c0 = *(const float4*)(p0);
        float4 c1 = *(const float4*)(p0 + LSTRIDE);
        float4 c2 = *(const float4*)(p0 + 2 * LSTRIDE);
        float4 c3 = *(const float4*)(p0 + 3 * LSTRIDE);
        float4 c4 = *(const float4*)(p1);
        float4 c5 = *(const float4*)(p1 + LSTRIDE);
        float4 c6 = *(const float4*)(p1 + 2 * LSTRIDE);
        float4 c7 = *(const float4*)(p1 + 3 * LSTRIDE);

        for (; w + 3 < whi; w += 2) {
            // Next pair: seg indices + 8 data loads issue before consume.
            const int nsg0 = __ldg(segr + w + 2);
            const int nsg1 = __ldg(segr + w + 3);
            const float* q0 = base + (size_t)(w + 2) * DD;
            const float* q1 = q0 + DD;
            float4 n0 = *(const float4*)(q0);
            float4 n1 = *(const float4*)(q0 + LSTRIDE);
            float4 n2 = *(const float4*)(q0 + 2 * LSTRIDE);
            float4 n3 = *(const float4*)(q0 + 3 * LSTRIDE);
            float4 n4 = *(const float4*)(q1);
            float4 n5 = *(const float4*)(q1 + LSTRIDE);
            float4 n6 = *(const float4*)(q1 + 2 * LSTRIDE);
            float4 n7 = *(const float4*)(q1 + 3 * LSTRIDE);

            rmw(sg0, sum4(c0, c1, c2, c3));
            rmw(sg1, sum4(c4, c5, c6, c7));

            sg0 = nsg0; sg1 = nsg1;
            c0 = n0; c1 = n1; c2 = n2; c3 = n3;
            c4 = n4; c5 = n5; c6 = n6; c7 = n7;
        }
        rmw(sg0, sum4(c0, c1, c2, c3));
        rmw(sg1, sum4(c4, c5, c6, c7));
        w += 2;
    }
    // Tail: 0 or 1 leftover subword.
    for (; w < whi; ++w) {
        const int sg = __ldg(segr + w);
        const float* p = base + (size_t)w * DD;
        float4 e0 = *(const float4*)(p);
        float4 e1 = *(const float4*)(p + LSTRIDE);
        float4 e2 = *(const float4*)(p + 2 * LSTRIDE);
        float4 e3 = *(const float4*)(p + 3 * LSTRIDE);
        rmw(sg, sum4(e0, e1, e2, e3));
    }

    // sent contribution (thread-owned columns, still barrier-free).
    {
        float4 cs = make_float4(0.f, 0.f, 0.f, 0.f);
        #pragma unroll
        for (int s = 0; s < TILE_S; ++s) {
            float4 v = ((const float4*)&tile_s[s][0])[tid];
            cs.x += v.x; cs.y += v.y; cs.z += v.z; cs.w += v.w;
        }
        const float k = 0.25f / (float)WW;
        float* sp = sent + b * DD + d0 + tid * 4;
        atomicAdd(sp + 0, cs.x * k);
        atomicAdd(sp + 1, cs.y * k);
        atomicAdd(sp + 2, cs.z * k);
        atomicAdd(sp + 3, cs.w * k);
    }

    __syncthreads();   // the ONLY barrier: transpose reads cross-thread data

    // Transposed coalesced write: word[b, d0+dd, s0 + ss4*4 .. +3] as float4.
    float* __restrict__ outb = word + ((size_t)b * DD + d0) * WW + s0;
    const int NOUT = (TILE_S / 4) * TILE_D;   // 1536 float4 stores
    for (int i2 = tid; i2 < NOUT; i2 += NTHR) {
        const int ss4 = i2 & 3;
        const int dd  = i2 >> 2;
        float4 v;
        v.x = 0.25f * tile_s[ss4 * 4 + 0][dd];
        v.y = 0.25f * tile_s[ss4 * 4 + 1][dd];
        v.z = 0.25f * tile_s[ss4 * 4 + 2][dd];
        v.w = 0.25f * tile_s[ss4 * 4 + 3][dd];
        *(float4*)(outb + (size_t)dd * WW + ss4 * 4) = v;
    }
}

extern "C" void kernel_launch(void* const* d_in, const int* in_sizes, int n_in,
                              void* d_out, int out_size) {
    const float* emb = (const float*)d_in[0];
    const int*   seg = (const int*)d_in[1];

    float* word = (float*)d_out;                   // [B, D, W]
    float* sent = word + (size_t)BB * DD * WW;     // [B, D]

    setup_kernel<<<BB, WW>>>(seg, sent);

    dim3 grid(DD / TILE_D, NT, BB);                // (2, 32, 32) = 2048 blocks
    word_agg_kernel<<<grid, NTHR>>>(emb, seg, word, sent);
}

// round 16
// speedup vs baseline: 1.4545x; 1.3084x over previous
#include <cuda_runtime.h>
#include <stdint.h>

// embeddings: [B=32, L=4, W=512, D=768] f32; segment_ids: [B=32, W=512] i32 sorted/row.
// Out (f32, concat): word [B, D, W] then sent [B, D].
//
// word[b,d,s] = (1/L) * sum_{w: seg[b,w]==s} sum_l emb[b,l,w,d]
// sent[b,d]   = (1/W) * sum_s word[b,d,s]
//
// R15 = R14 + __launch_bounds__(NTHR, 6): the 113-reg budget lets ptxas keep
// the full depth-1 pipeline (8 in-flight float4 + 8 consuming = ~64 data
// regs) without de-pipelining. Occupancy deliberately traded down — on this
// kernel the register budget IS the pipeline (R9/R15 evidence).

#define BB 32
#define LL 4
#define WW 512
#define DD 768

#define TILE_S 16             // segments per block
#define NT     (WW / TILE_S)  // 32 s-tiles per row
#define NTHR   96             // threads per block
#define TILE_D (NTHR * 4)     // 384 d-channels per block (float4/thread)
#define TS_ST  388            // tile_s row stride (floats)

// bounds[b][t] = first w with seg[b,w] >= t*TILE_S (== W if none).
__device__ int g_bounds[BB][NT + 1];

__global__ void setup_kernel(const int* __restrict__ seg,
                             float* __restrict__ sent) {
    const int b   = blockIdx.x;
    const int tid = threadIdx.x;   // 512 threads

    for (int i = b * blockDim.x + tid; i < BB * DD; i += gridDim.x * blockDim.x)
        sent[i] = 0.0f;

    if (tid <= NT) g_bounds[b][tid] = WW;
    __syncthreads();

    const int v    = seg[b * WW + tid];
    const int prev = (tid == 0) ? -1 : seg[b * WW + tid - 1];
    const int t_lo = (prev < 0) ? 0 : (prev / TILE_S + 1);
    const int t_hi = v / TILE_S;
    for (int t = t_lo; t <= t_hi && t <= NT; ++t)
        g_bounds[b][t] = tid;
}

__device__ __forceinline__ float4 sum4(float4 a, float4 b, float4 c, float4 d) {
    float4 r;
    r.x = (a.x + b.x) + (c.x + d.x);
    r.y = (a.y + b.y) + (c.y + d.y);
    r.z = (a.z + b.z) + (c.z + d.z);
    r.w = (a.w + b.w) + (c.w + d.w);
    return r;
}

__global__ __launch_bounds__(NTHR, 6)
void word_agg_kernel(const float* __restrict__ emb,
                     const int*   __restrict__ seg,
                     float*       __restrict__ word,   // [B, D, W]
                     float*       __restrict__ sent)   // [B, D]
{
    __shared__ float tile_s[TILE_S][TS_ST];   // 16 x 388 x 4B = 24,832 B

    const int b   = blockIdx.z;
    const int ty  = blockIdx.y;               // s-tile index
    const int s0  = ty * TILE_S;
    const int d0  = blockIdx.x * TILE_D;
    const int tid = threadIdx.x;

    // Zero thread-owned tile_s columns — no barrier needed (column [*][tid]
    // is written and read only by this thread until the transpose).
    #pragma unroll
    for (int s = 0; s < TILE_S; ++s)
        ((float4*)&tile_s[s][0])[tid] = make_float4(0.f, 0.f, 0.f, 0.f);

    // Precomputed w-range: 2 uniform cached loads, no scan, no barrier.
    const int wlo = __ldg(&g_bounds[b][ty]);
    const int whi = __ldg(&g_bounds[b][ty + 1]);

    const float* __restrict__ base = emb + ((size_t)b * LL * WW) * DD + d0 + tid * 4;
    const int*   __restrict__ segr = seg + b * WW;
    const size_t LSTRIDE = (size_t)WW * DD;

    // Consume path: pure register -> LDS/FADD/STS (seg index already in reg).
    auto rmw = [&](int sidx, float4 v) {
        float4* row = (float4*)&tile_s[sidx - s0][0];
        float4 t = row[tid];
        t.x += v.x; t.y += v.y; t.z += v.z; t.w += v.w;
        row[tid] = t;
    };

    int w = wlo;
    if (w + 1 < whi) {
        // Pipeline prologue: data pair (w, w+1) = 8 LDG.128, plus the pair's
        // seg indices — ALL in flight before any consume.
        const float* p0 = base + (size_t)w * DD;
        const float* p1 = p0 + DD;
        int sg0 = __ldg(segr + w);
        int sg1 = __ldg(segr + w + 1);
        float4 c0 = *(const float4*)(p0);
        float4 c1 = *(const float4*)(p0 + LSTRIDE);
        float4 c2 = *(const float4*)(p0 + 2 * LSTRIDE);
        float4 c3 = *(const float4*)(p0 + 3 * LSTRIDE);
        float4 c4 = *(const float4*)(p1);
        float4 c5 = *(const float4*)(p1 + LSTRIDE);
        float4 c6 = *(const float4*)(p1 + 2 * LSTRIDE);
        float4 c7 = *(const float4*)(p1 + 3 * LSTRIDE);

        for (; w + 3 < whi; w += 2) {
            // Next pair: seg indices + 8 data loads issue before consume.
            const int nsg0 = __ldg(segr + w + 2);
            const int nsg1 = __ldg(segr + w + 3);
            const float* q0 = base + (size_t)(w + 2) * DD;
            const float* q1 = q0 + DD;
            float4 n0 = *(const float4*)(q0);
            float4 n1 = *(const float4*)(q0 + LSTRIDE);
            float4 n2 = *(const float4*)(q0 + 2 * LSTRIDE);
            float4 n3 = *(const float4*)(q0 + 3 * LSTRIDE);
            float4 n4 = *(const float4*)(q1);
            float4 n5 = *(const float4*)(q1 + LSTRIDE);
            float4 n6 = *(const float4*)(q1 + 2 * LSTRIDE);
            float4 n7 = *(const float4*)(q1 + 3 * LSTRIDE);

            rmw(sg0, sum4(c0, c1, c2, c3));
            rmw(sg1, sum4(c4, c5, c6, c7));

            sg0 = nsg0; sg1 = nsg1;
            c0 = n0; c1 = n1; c2 = n2; c3 = n3;
            c4 = n4; c5 = n5; c6 = n6; c7 = n7;
        }
        rmw(sg0, sum4(c0, c1, c2, c3));
        rmw(sg1, sum4(c4, c5, c6, c7));
        w += 2;
    }
    // Tail: 0 or 1 leftover subword.
    for (; w < whi; ++w) {
        const int sg = __ldg(segr + w);
        const float* p = base + (size_t)w * DD;
        float4 e0 = *(const float4*)(p);
        float4 e1 = *(const float4*)(p + LSTRIDE);
        float4 e2 = *(const float4*)(p + 2 * LSTRIDE);
        float4 e3 = *(const float4*)(p + 3 * LSTRIDE);
        rmw(sg, sum4(e0, e1, e2, e3));
    }

    // sent contribution (thread-owned columns, still barrier-free).
    {
        float4 cs = make_float4(0.f, 0.f, 0.f, 0.f);
        #pragma unroll
        for (int s = 0; s < TILE_S; ++s) {
            float4 v = ((const float4*)&tile_s[s][0])[tid];
            cs.x += v.x; cs.y += v.y; cs.z += v.z; cs.w += v.w;
        }
        const float k = 0.25f / (float)WW;
        float* sp = sent + b * DD + d0 + tid * 4;
        atomicAdd(sp + 0, cs.x * k);
        atomicAdd(sp + 1, cs.y * k);
        atomicAdd(sp + 2, cs.z * k);
        atomicAdd(sp + 3, cs.w * k);
    }

    __syncthreads();   // the ONLY barrier: transpose reads cross-thread data

    // Transposed coalesced write: word[b, d0+dd, s0 + ss4*4 .. +3] as float4.
    float* __restrict__ outb = word + ((size_t)b * DD + d0) * WW + s0;
    const int NOUT = (TILE_S / 4) * TILE_D;   // 1536 float4 stores
    for (int i2 = tid; i2 < NOUT; i2 += NTHR) {
        const int ss4 = i2 & 3;
        const int dd  = i2 >> 2;
        float4 v;
        v.x = 0.25f * tile_s[ss4 * 4 + 0][dd];
        v.y = 0.25f * tile_s[ss4 * 4 + 1][dd];
        v.z = 0.25f * tile_s[ss4 * 4 + 2][dd];
        v.w = 0.25f * tile_s[ss4 * 4 + 3][dd];
        *(float4*)(outb + (size_t)dd * WW + ss4 * 4) = v;
    }
}

extern "C" void kernel_launch(void* const* d_in, const int* in_sizes, int n_in,
                              void* d_out, int out_size) {
    const float* emb = (const float*)d_in[0];
    const int*   seg = (const int*)d_in[1];

    float* word = (float*)d_out;                   // [B, D, W]
    float* sent = word + (size_t)BB * DD * WW;     // [B, D]

    setup_kernel<<<BB, WW>>>(seg, sent);

    dim3 grid(DD / TILE_D, NT, BB);                // (2, 32, 32) = 2048 blocks
    word_agg_kernel<<<grid, NTHR>>>(emb, seg, word, sent);
}